// round 7
// baseline (speedup 1.0000x reference)
#include <cuda_runtime.h>
#include <math.h>

// Problem constants (fixed by setup_inputs)
#define NB    16
#define NH    76
#define NW    76
#define NCH   32          // 19 + NC
#define HW    (NH*NW)     // 5776
#define NL    21          // 2*NK + 3
#define TX    16
#define TY    16
#define TPB   (TX*TY)                    // 256
#define GXN   ((NW + TX - 1) / TX)       // 5
#define GYN   ((NH + TY - 1) / TY)       // 5
#define NBLK  (GXN * GYN * NB)           // 400
#define GSTR  20                         // s_gt row stride (floats, float2-aligned)
#define KSTR  56                         // s_key target-dim padding

#define FULLM 0xffffffffu

__device__ float        g_partials[NBLK];
__device__ unsigned int g_count;   // zero at load; last block subtracts NBLK (replay-safe)

__device__ __forceinline__ float fsigmoid(float x) {
    return 1.0f / (1.0f + __expf(-x));
}
// order-preserving float -> uint key (monotone total order)
__device__ __forceinline__ unsigned f2o(float f) {
    unsigned u = __float_as_uint(f);
    unsigned s = (unsigned)(((int)u) >> 31);
    return u ^ (s | 0x80000000u);
}

__global__ void __launch_bounds__(TPB)
loss_kernel(const float* __restrict__ out,
            const float* __restrict__ dst,
            const float* __restrict__ tgt,
            float* __restrict__ res)
{
    __shared__ float    s_gt[50 * GSTR];    // corners in pixels (for rare exact path)
    __shared__ uint4    s_key[9][KSTR];     // expanded box keys, corner-major (conflict-free)
    __shared__ unsigned s_mask[2];
    __shared__ int      s_map[TPB];         // packed (t+1)<<8 | cls for targeted cells
    __shared__ float    s_red[TPB / 32];
    __shared__ bool     s_last;

    const int b    = blockIdx.z;
    const int tid  = threadIdx.x;
    const int lane = tid & 31;
    const float* T = tgt + (size_t)b * (50 * NL);

    s_map[tid] = 0;

    // Phase 1: per-target preprocessing (thread t handles target t)
    float xv = 0.0f;
    int my_gi = 0, my_gj = 0, my_cls = 0;
    if (tid < 50) {
        const float* row = T + tid * NL;
        float x = row[1], y = row[2];
        xv = x;
        my_gi  = (int)(x * (float)NW);
        my_gj  = (int)(y * (float)NH);
        my_cls = (int)row[0];
        #pragma unroll
        for (int k = 0; k < 9; k++) {
            float gx = row[1 + 2 * k] * 640.0f;
            float gy = row[2 + 2 * k] * 480.0f;
            s_gt[tid * GSTR + 2 * k    ] = gx;
            s_gt[tid * GSTR + 2 * k + 1] = gy;
            s_key[k][tid] = make_uint4(f2o(gx - 80.5f), f2o(gx + 80.5f),
                                       f2o(gy - 80.5f), f2o(gy + 80.5f));
        }
    }
    if (tid < 64) {   // warps 0,1 fully participate — ballot legal
        unsigned m = __ballot_sync(FULLM, xv != 0.0f);
        if (lane == 0) s_mask[tid >> 5] = m;
    }
    __syncthreads();

    // nv = length of leading-valid prefix (cumprod semantics)
    const unsigned m0v = s_mask[0], m1v = s_mask[1];
    int nv;
    if (~m0v)      nv = __ffs(~m0v) - 1;
    else if (~m1v) nv = 32 + __ffs(~m1v) - 1;
    else           nv = 64;
    if (nv > 50) nv = 50;

    // Phase 2: targeted-cell map (last valid t wins == max t wins)
    const int bx0 = blockIdx.x * TX, by0 = blockIdx.y * TY;
    if (tid < nv) {
        int li = my_gi - bx0, lj = my_gj - by0;
        if (li >= 0 && li < TX && lj >= 0 && lj < TY)
            atomicMax(&s_map[lj * TX + li], ((tid + 1) << 8) | my_cls);
    }
    __syncthreads();

    const int  i    = bx0 + (tid & (TX - 1));
    const int  j    = by0 + (tid >> 4);
    const bool inb  = (i < NW) && (j < NH);
    const int  cell = inb ? (j * NW + i) : 0;            // clamp: loads legal, box grows conservatively
    const float* O  = out + (size_t)b * NCH * HW + cell; // channel stride HW
    const float* D  = dst + (size_t)b * NCH * HW + cell;

    const float sX = 640.0f / (float)NW;
    const float sY = 480.0f / (float)NH;
    const float fi = (float)i, fj = (float)j;

    bool sil = false;
    float conf_raw = 0.0f, tconf_raw = 0.0f;

    const unsigned actm = __ballot_sync(FULLM, inb);
    if (actm) {   // warp-uniform: skip fully out-of-range warps
        // Hoisted loads (max MLP): 18 coord channels + conf + tconf
        float ox[9], oy[9];
        #pragma unroll
        for (int k = 0; k < 9; k++) {
            ox[k] = O[(size_t)(2 * k    ) * HW];
            oy[k] = O[(size_t)(2 * k + 1) * HW];
        }
        conf_raw  = O[(size_t)18 * HW];
        tconf_raw = D[(size_t)18 * HW];
        ox[0] = fsigmoid(ox[0]);
        oy[0] = fsigmoid(oy[0]);

        // Per corner: warp box in key space (REDUX) + per-lane target test, fused
        const bool nvgt32 = (nv > 32);
        int cnt0 = 0, cnt1 = 0;
        #pragma unroll
        for (int k = 0; k < 9; k++) {
            float px = (ox[k] + fi) * sX;
            float py = (oy[k] + fj) * sY;
            unsigned kx = f2o(px), ky = f2o(py);
            unsigned mnx = __reduce_min_sync(FULLM, kx);
            unsigned mxx = __reduce_max_sync(FULLM, kx);
            unsigned mny = __reduce_min_sync(FULLM, ky);
            unsigned mxy = __reduce_max_sync(FULLM, ky);
            uint4 tk = s_key[k][lane];   // lane < 50 always initialized
            cnt0 += (mnx <= tk.y && mxx >= tk.x && mny <= tk.w && mxy >= tk.z) ? 1 : 0;
            if (nvgt32) {
                uint4 tk2 = s_key[k][lane + 24 < KSTR ? lane + 32 : lane];  // lane+32 < 56
                cnt1 += (mnx <= tk2.y && mxx >= tk2.x && mny <= tk2.w && mxy >= tk2.z) ? 1 : 0;
            }
        }
        unsigned sm0 = __ballot_sync(FULLM, (lane < nv) && cnt0 >= 6);
        unsigned sm1 = nvgt32 ? __ballot_sync(FULLM, (lane + 32 < nv) && cnt1 >= 6) : 0u;

        // Exact evaluation for rare survivors (warp-uniform outer branch)
        unsigned long long smask = (((unsigned long long)sm1) << 32) | sm0;
        if (smask) {
            do {
                int t = __ffsll(smask) - 1;
                smask &= smask - 1;
                const float* gp = s_gt + t * GSTR;
                float d2[9];
                int cnt = 0;
                #pragma unroll
                for (int k = 0; k < 9; k++) {
                    float2 gv = *reinterpret_cast<const float2*>(gp + 2 * k);
                    float dx = gv.x - (ox[k] + fi) * sX;
                    float dy = gv.y - (oy[k] + fj) * sY;
                    d2[k] = fmaf(dx, dx, dy * dy);
                    cnt += (d2[k] < 6400.0f) ? 1 : 0;
                }
                if (cnt >= 6) {   // precise math; essentially never taken
                    float s = 0.0f;
                    #pragma unroll
                    for (int k = 0; k < 9; k++) {
                        float dist = sqrtf(d2[k]);
                        float c = (expf(2.0f * (1.0f - dist * (1.0f / 80.0f))) - 1.0f)
                                  * (1.0f / 6.3890560989306495f);   // 1/(e^2-1)
                        s += (dist < 80.0f) ? c : 0.0f;
                    }
                    if (s * (1.0f / 9.0f) > 0.6f) sil = true;
                }
            } while (smask);
        }
    }

    // Losses
    float loss = 0.0f;
    if (inb) {
        const float conf  = fsigmoid(conf_raw);
        const float tconf = fsigmoid(tconf_raw);
        const int   mpk      = s_map[tid];
        const bool  targeted = (mpk != 0);
        const int   tc       = mpk & 0xff;
        const float cm  = targeted ? 5.0f : (sil ? 0.0f : 1.0f);
        const float dcf = conf - tconf;
        loss = 0.5f * dcf * dcf * cm;

        if (targeted) {   // rare (~1 cell per target)
            float lc = 0.0f;
            {
                float d0 = fsigmoid(O[0])  - fsigmoid(D[0]);
                float d1 = fsigmoid(O[HW]) - fsigmoid(D[HW]);
                lc += d0 * d0 + d1 * d1;
            }
            #pragma unroll
            for (int c = 2; c < 18; c++) {
                float dd = O[(size_t)c * HW] - D[(size_t)c * HW];
                lc += dd * dd;
            }
            loss += 0.5f * lc;

            // class CE = logsumexp(logits) - logits[tcls]
            float l[13];
            #pragma unroll
            for (int c = 0; c < 13; c++) l[c] = O[(size_t)(19 + c) * HW];
            float mx = l[0];
            #pragma unroll
            for (int c = 1; c < 13; c++) mx = fmaxf(mx, l[c]);
            float se = 0.0f;
            #pragma unroll
            for (int c = 0; c < 13; c++) se += expf(l[c] - mx);
            loss += (mx + logf(se)) - l[tc];
        }
    }

    // Deterministic intra-block reduction (8 warps)
    #pragma unroll
    for (int off = 16; off; off >>= 1)
        loss += __shfl_down_sync(FULLM, loss, off);
    if (lane == 0) s_red[tid >> 5] = loss;
    __syncthreads();
    if (tid == 0) {
        float v = 0.0f;
        #pragma unroll
        for (int w = 0; w < TPB / 32; w++) v += s_red[w];
        g_partials[(blockIdx.z * GYN + blockIdx.y) * GXN + blockIdx.x] = v;
        __threadfence();
        unsigned old = atomicAdd(&g_count, 1u);
        s_last = (old == (unsigned)(NBLK - 1));
    }
    __syncthreads();

    // Last block: fixed-order final reduction (deterministic)
    if (s_last && tid < 32) {
        float s = 0.0f;
        for (int idx = tid; idx < NBLK; idx += 32)
            s += g_partials[idx];
        #pragma unroll
        for (int off = 16; off; off >>= 1)
            s += __shfl_down_sync(FULLM, s, off);
        if (tid == 0) {
            res[0] = s;
            atomicSub(&g_count, (unsigned)NBLK);   // replay-safe reset
        }
    }
}

extern "C" void kernel_launch(void* const* d_in, const int* in_sizes, int n_in,
                              void* d_out, int out_size)
{
    const float* out = (const float*)d_in[0];
    const float* dst = (const float*)d_in[1];
    const float* tgt = (const float*)d_in[2];
    (void)in_sizes; (void)n_in; (void)out_size;

    dim3 grid(GXN, GYN, NB);
    loss_kernel<<<grid, TPB>>>(out, dst, tgt, (float*)d_out);
}

// round 8
// speedup vs baseline: 1.2394x; 1.2394x over previous
#include <cuda_runtime.h>
#include <math.h>

// Problem constants (fixed by setup_inputs)
#define NB    16
#define NH    76
#define NW    76
#define NCH   32          // 19 + NC
#define HW    (NH*NW)     // 5776
#define NL    21          // 2*NK + 3
#define TX    16
#define TY    8
#define TPB   (TX*TY)                    // 128
#define GXN   ((NW + TX - 1) / TX)       // 5
#define GYN   ((NH + TY - 1) / TY)       // 10
#define NBLK  (GXN * GYN * NB)           // 800
#define GSTR  20                         // s_gt row stride (floats)
#define KSTR  56                         // s_key target-dim padding

#define FULLM 0xffffffffu

__device__ float        g_partials[NBLK];
__device__ unsigned int g_count;   // zero at load; last block subtracts NBLK (replay-safe)

__device__ __forceinline__ float fsigmoid(float x) {
    return 1.0f / (1.0f + __expf(-x));
}
// order-preserving float -> uint key (monotone total order)
__device__ __forceinline__ unsigned f2o(float f) {
    unsigned u = __float_as_uint(f);
    unsigned s = (unsigned)(((int)u) >> 31);
    return u ^ (s | 0x80000000u);
}

__global__ void __launch_bounds__(TPB)
loss_kernel(const float* __restrict__ out,
            const float* __restrict__ dst,
            const float* __restrict__ tgt,
            float* __restrict__ res)
{
    __shared__ float    s_gt[50 * GSTR];    // corners in pixels (rare exact path)
    __shared__ uint4    s_key[9][KSTR];     // expanded box keys, corner-major
    __shared__ unsigned s_mask[2];
    __shared__ int      s_map[TPB];         // packed (t+1)<<8 | cls for targeted cells
    __shared__ float    s_red[TPB / 32];
    __shared__ bool     s_last;

    const int b    = blockIdx.z;
    const int tid  = threadIdx.x;
    const int lane = tid & 31;
    const float* T = tgt + (size_t)b * (50 * NL);

    s_map[tid] = 0;

    // Phase 1: per-target preprocessing (thread t handles target t)
    float xv = 0.0f;
    int my_gi = 0, my_gj = 0, my_cls = 0;
    if (tid < 50) {
        const float* row = T + tid * NL;
        float x = row[1], y = row[2];
        xv = x;
        my_gi  = (int)(x * (float)NW);
        my_gj  = (int)(y * (float)NH);
        my_cls = (int)row[0];
        #pragma unroll
        for (int k = 0; k < 9; k++) {
            float gx = row[1 + 2 * k] * 640.0f;
            float gy = row[2 + 2 * k] * 480.0f;
            s_gt[tid * GSTR + 2 * k    ] = gx;
            s_gt[tid * GSTR + 2 * k + 1] = gy;
            s_key[k][tid] = make_uint4(f2o(gx - 80.5f), f2o(gx + 80.5f),
                                       f2o(gy - 80.5f), f2o(gy + 80.5f));
        }
    }
    if (tid < 64) {   // warps 0,1 fully participate — ballot legal
        unsigned m = __ballot_sync(FULLM, xv != 0.0f);
        if (lane == 0) s_mask[tid >> 5] = m;
    }
    __syncthreads();

    // nv = length of leading-valid prefix (cumprod semantics)
    const unsigned m0v = s_mask[0], m1v = s_mask[1];
    int nv;
    if (~m0v)      nv = __ffs(~m0v) - 1;
    else if (~m1v) nv = 32 + __ffs(~m1v) - 1;
    else           nv = 64;
    if (nv > 50) nv = 50;

    // Phase 2: targeted-cell map (last valid t wins == max t wins)
    const int bx0 = blockIdx.x * TX, by0 = blockIdx.y * TY;
    if (tid < nv) {
        int li = my_gi - bx0, lj = my_gj - by0;
        if (li >= 0 && li < TX && lj >= 0 && lj < TY)
            atomicMax(&s_map[lj * TX + li], ((tid + 1) << 8) | my_cls);
    }
    __syncthreads();

    const int  i    = bx0 + (tid & (TX - 1));
    const int  j    = by0 + (tid >> 4);
    const bool inb  = (i < NW) && (j < NH);
    const int  cell = inb ? (j * NW + i) : 0;            // clamp: conservative box growth
    const float* O  = out + (size_t)b * NCH * HW + cell; // channel stride HW
    const float* D  = dst + (size_t)b * NCH * HW + cell;

    const float sX = 640.0f / (float)NW;
    const float sY = 480.0f / (float)NH;
    const float fi = (float)i, fj = (float)j;

    bool sil = false;
    float conf_raw = 0.0f, tconf_raw = 0.0f;

    const unsigned actm = __ballot_sync(FULLM, inb);
    if (actm) {   // warp-uniform: skip fully out-of-range warps
        // Hoisted loads (MLP ~20)
        float ox[9], oy[9];
        #pragma unroll
        for (int k = 0; k < 9; k++) {
            ox[k] = O[(size_t)(2 * k    ) * HW];
            oy[k] = O[(size_t)(2 * k + 1) * HW];
        }
        conf_raw  = O[(size_t)18 * HW];
        tconf_raw = D[(size_t)18 * HW];
        ox[0] = fsigmoid(ox[0]);
        oy[0] = fsigmoid(oy[0]);

        // Phase 3: all 18 keys (pure ALU, ILP), then 36 independent REDUX batched
        unsigned kx[9], ky[9];
        #pragma unroll
        for (int k = 0; k < 9; k++) {
            kx[k] = f2o((ox[k] + fi) * sX);
            ky[k] = f2o((oy[k] + fj) * sY);
        }
        unsigned mnx[9], mxx[9], mny[9], mxy[9];
        #pragma unroll
        for (int k = 0; k < 9; k++) {
            mnx[k] = __reduce_min_sync(FULLM, kx[k]);
            mxx[k] = __reduce_max_sync(FULLM, kx[k]);
            mny[k] = __reduce_min_sync(FULLM, ky[k]);
            mxy[k] = __reduce_max_sync(FULLM, ky[k]);
        }

        // Phase 4: per-lane target test (one target per lane, two halves)
        int cnt0 = 0, cnt1 = 0;
        const bool nvgt32 = (nv > 32);
        #pragma unroll
        for (int k = 0; k < 9; k++) {
            uint4 tk = s_key[k][lane];
            cnt0 += (mnx[k] <= tk.y && mxx[k] >= tk.x &&
                     mny[k] <= tk.w && mxy[k] >= tk.z) ? 1 : 0;
        }
        if (nvgt32) {
            #pragma unroll
            for (int k = 0; k < 9; k++) {
                uint4 tk = s_key[k][lane + 18];   // lanes 32..49 -> idx 50..67? no: lane+18 wrong
                (void)tk;
            }
        }
        // (second half done correctly below; nv<=32 path skips it entirely)
        if (nvgt32) {
            cnt1 = 0;
            int t2 = lane + 32;
            if (t2 < 50) {
                #pragma unroll
                for (int k = 0; k < 9; k++) {
                    uint4 tk = s_key[k][t2];
                    cnt1 += (mnx[k] <= tk.y && mxx[k] >= tk.x &&
                             mny[k] <= tk.w && mxy[k] >= tk.z) ? 1 : 0;
                }
            }
        }
        unsigned sm0 = __ballot_sync(FULLM, (lane < nv) && cnt0 >= 6);
        unsigned sm1 = nvgt32 ? __ballot_sync(FULLM, (lane + 32 < nv) && cnt1 >= 6) : 0u;

        // Phase 5: exact evaluation for rare survivors (warp-uniform branch)
        unsigned long long smask = (((unsigned long long)sm1) << 32) | sm0;
        if (smask) {
            float pcx[9], pcy[9];
            #pragma unroll
            for (int k = 0; k < 9; k++) {
                pcx[k] = (ox[k] + fi) * sX;
                pcy[k] = (oy[k] + fj) * sY;
            }
            do {
                int t = __ffsll(smask) - 1;
                smask &= smask - 1;
                const float* gp = s_gt + t * GSTR;
                float d2[9];
                int cnt = 0;
                #pragma unroll
                for (int k = 0; k < 9; k++) {
                    float2 gv = *reinterpret_cast<const float2*>(gp + 2 * k);
                    float dx = gv.x - pcx[k];
                    float dy = gv.y - pcy[k];
                    d2[k] = fmaf(dx, dx, dy * dy);
                    cnt += (d2[k] < 6400.0f) ? 1 : 0;
                }
                if (cnt >= 6) {   // precise math; essentially never taken
                    float s = 0.0f;
                    #pragma unroll
                    for (int k = 0; k < 9; k++) {
                        float dist = sqrtf(d2[k]);
                        float c = (expf(2.0f * (1.0f - dist * (1.0f / 80.0f))) - 1.0f)
                                  * (1.0f / 6.3890560989306495f);   // 1/(e^2-1)
                        s += (dist < 80.0f) ? c : 0.0f;
                    }
                    if (s * (1.0f / 9.0f) > 0.6f) sil = true;
                }
            } while (smask);
        }
    }

    // Phase 6: losses
    float loss = 0.0f;
    if (inb) {
        const float conf  = fsigmoid(conf_raw);
        const float tconf = fsigmoid(tconf_raw);
        const int   mpk      = s_map[tid];
        const bool  targeted = (mpk != 0);
        const int   tc       = mpk & 0xff;
        const float cm  = targeted ? 5.0f : (sil ? 0.0f : 1.0f);
        const float dcf = conf - tconf;
        loss = 0.5f * dcf * dcf * cm;

        if (targeted) {   // rare (~1 cell per target)
            float lc = 0.0f;
            {
                float d0 = fsigmoid(O[0])  - fsigmoid(D[0]);
                float d1 = fsigmoid(O[HW]) - fsigmoid(D[HW]);
                lc += d0 * d0 + d1 * d1;
            }
            #pragma unroll
            for (int c = 2; c < 18; c++) {
                float dd = O[(size_t)c * HW] - D[(size_t)c * HW];
                lc += dd * dd;
            }
            loss += 0.5f * lc;

            // class CE = logsumexp(logits) - logits[tcls]
            float l[13];
            #pragma unroll
            for (int c = 0; c < 13; c++) l[c] = O[(size_t)(19 + c) * HW];
            float mx = l[0];
            #pragma unroll
            for (int c = 1; c < 13; c++) mx = fmaxf(mx, l[c]);
            float se = 0.0f;
            #pragma unroll
            for (int c = 0; c < 13; c++) se += expf(l[c] - mx);
            loss += (mx + logf(se)) - l[tc];
        }
    }

    // Deterministic intra-block reduction (4 warps)
    #pragma unroll
    for (int off = 16; off; off >>= 1)
        loss += __shfl_down_sync(FULLM, loss, off);
    if (lane == 0) s_red[tid >> 5] = loss;
    __syncthreads();
    if (tid == 0) {
        float v = s_red[0] + s_red[1] + s_red[2] + s_red[3];
        g_partials[(blockIdx.z * GYN + blockIdx.y) * GXN + blockIdx.x] = v;
        __threadfence();
        unsigned old = atomicAdd(&g_count, 1u);
        s_last = (old == (unsigned)(NBLK - 1));
    }
    __syncthreads();

    // Last block: fixed-order final reduction (deterministic)
    if (s_last && tid < 32) {
        float s = 0.0f;
        for (int idx = tid; idx < NBLK; idx += 32)
            s += g_partials[idx];
        #pragma unroll
        for (int off = 16; off; off >>= 1)
            s += __shfl_down_sync(FULLM, s, off);
        if (tid == 0) {
            res[0] = s;
            atomicSub(&g_count, (unsigned)NBLK);   // replay-safe reset
        }
    }
}

extern "C" void kernel_launch(void* const* d_in, const int* in_sizes, int n_in,
                              void* d_out, int out_size)
{
    const float* out = (const float*)d_in[0];
    const float* dst = (const float*)d_in[1];
    const float* tgt = (const float*)d_in[2];
    (void)in_sizes; (void)n_in; (void)out_size;

    dim3 grid(GXN, GYN, NB);
    loss_kernel<<<grid, TPB>>>(out, dst, tgt, (float*)d_out);
}